// round 8
// baseline (speedup 1.0000x reference)
#include <cuda_runtime.h>
#include <cstdint>

#define B_ 8
#define C_ 32
#define N_ 4096
#define KC 64
#define SPLIT 4

__device__ float g_e[B_ * N_];
__device__ float g_part[SPLIT][B_ * C_ * N_];

__global__ void mean_exp_kernel(const float* __restrict__ x) {
    int idx = blockIdx.x * blockDim.x + threadIdx.x;
    if (idx >= B_ * N_) return;
    int b = idx >> 12, n = idx & (N_ - 1);
    const float* p = x + ((size_t)b * C_) * N_ + n;
    float s = 0.f;
#pragma unroll
    for (int c = 0; c < C_; c++) s += p[(size_t)c * N_];
    g_e[idx] = __expf(s * (1.0f / C_));
}

__device__ __forceinline__ uint32_t to_tf32(float f) {
    uint32_t u;
    asm("cvt.rna.tf32.f32 %0, %1;" : "=r"(u) : "f"(f));
    return u;
}

#define MMA_TF32(acc, a, b0v, b1v)                                          \
    asm volatile(                                                           \
        "mma.sync.aligned.m16n8k8.row.col.f32.tf32.tf32.f32 "               \
        "{%0,%1,%2,%3}, {%4,%5,%6,%7}, {%8,%9}, {%0,%1,%2,%3};"             \
        : "+f"((acc)[0]), "+f"((acc)[1]), "+f"((acc)[2]), "+f"((acc)[3])    \
        : "r"((a)[0]), "r"((a)[1]), "r"((a)[2]), "r"((a)[3]),               \
          "r"(b0v), "r"(b1v))

// W[m,n] = min(e_n,e_m)/(e_n+e_m) * adj[n,m]  (global x2 folded into combine)
// out^T[m,c] = 2 * para * sum_n W[m,n] * fea[c,n]
__global__ __launch_bounds__(256, 2)
void gcn_mma_kernel(const float* __restrict__ x,
                    const float* __restrict__ adj) {
    __shared__ uint32_t s_B[2][32 * KC];   // [batch][c*64 + swz(n)], tf32
    __shared__ float s_e[2][KC];

    const int tid = threadIdx.x;
    const int warp = tid >> 5;
    const int lane = tid & 31;
    const int q = lane >> 2;
    const int r = lane & 3;
    const int mb = blockIdx.x * 128 + warp * 16;
    const int bp = blockIdx.y;
    const int b0 = 2 * bp, b1 = 2 * bp + 1;
    const int z = blockIdx.z;
    const int nbeg = z * (N_ / SPLIT);
    const int nend = nbeg + (N_ / SPLIT);

    const float em0a = g_e[b0 * N_ + mb + q];
    const float em0b = g_e[b0 * N_ + mb + q + 8];
    const float em1a = g_e[b1 * N_ + mb + q];
    const float em1b = g_e[b1 * N_ + mb + q + 8];

    float acc[2][4][4];
#pragma unroll
    for (int bi = 0; bi < 2; bi++)
#pragma unroll
        for (int cf = 0; cf < 4; cf++)
#pragma unroll
            for (int i = 0; i < 4; i++) acc[bi][cf][i] = 0.f;

    // staging map: 2*32*64 = 4096 elems / 256 thr = 16 each (4 x float4)
    const int st_b = tid >> 7;
    const int st_c = (tid >> 2) & 31;
    const int st_ng = (tid & 3) * 16;
    const float* st_x = x + (((size_t)(2 * bp + st_b) * C_ + st_c) << 12);
    const int st_sw = 4 * (st_c & 7);

    for (int n0 = nbeg; n0 < nend; n0 += KC) {
        __syncthreads();
        {
            uint32_t* dst = &s_B[st_b][st_c * KC];
#pragma unroll
            for (int j = 0; j < 4; j++) {
                float4 u = *reinterpret_cast<const float4*>(st_x + n0 + st_ng + 4 * j);
                uint4 t;
                t.x = to_tf32(u.x); t.y = to_tf32(u.y);
                t.z = to_tf32(u.z); t.w = to_tf32(u.w);
                int w = (st_ng + 4 * j + st_sw) & (KC - 1);
                *reinterpret_cast<uint4*>(&dst[w]) = t;
            }
            if (tid < 128)
                s_e[tid >> 6][tid & 63] =
                    g_e[(2 * bp + (tid >> 6)) * N_ + n0 + (tid & 63)];
        }
        __syncthreads();

        const float* ap = adj + (size_t)(n0 + r) * N_ + mb + q;

        float adjA[4], adjB[4];
#define PRELOAD(BUF, KS)                                                    \
        {                                                                   \
            const float* apn = ap + (size_t)((KS) * 8) * N_;                \
            BUF[0] = __ldg(apn);                                            \
            BUF[1] = __ldg(apn + 8);                                        \
            BUF[2] = __ldg(apn + (size_t)4 * N_);                           \
            BUF[3] = __ldg(apn + (size_t)4 * N_ + 8);                       \
        }
#define COMPUTE(BUF, KS)                                                    \
        {                                                                   \
            const int k0 = (KS) * 8;                                        \
            const float en0_0 = s_e[0][k0 + r];                             \
            const float en0_4 = s_e[0][k0 + r + 4];                         \
            const float en1_0 = s_e[1][k0 + r];                             \
            const float en1_4 = s_e[1][k0 + r + 4];                         \
            uint32_t a0f[4], a1f[4];                                        \
            _Pragma("unroll")                                               \
            for (int s = 0; s < 4; s++) {                                   \
                const float en0 = (s < 2) ? en0_0 : en0_4;                  \
                const float en1 = (s < 2) ? en1_0 : en1_4;                  \
                const float e0 = (s & 1) ? em0b : em0a;                     \
                const float e1 = (s & 1) ? em1b : em1a;                     \
                float d0 = en0 + e0, d1 = en1 + e1;                         \
                float rr;                                                   \
                asm("rcp.approx.f32 %0, %1;" : "=f"(rr) : "f"(d0 * d1));    \
                float t = BUF[s] * rr;                                      \
                a0f[s] = to_tf32(fminf(en0, e0) * d1 * t);                  \
                a1f[s] = to_tf32(fminf(en1, e1) * d0 * t);                  \
            }                                                               \
            const int off0 = (k0 + r + 4 * q) & (KC - 1);                   \
            const int off4 = (k0 + r + 4 + 4 * q) & (KC - 1);               \
            _Pragma("unroll")                                               \
            for (int cf = 0; cf < 4; cf++) {                                \
                const int row = (cf * 8 + q) * KC;                          \
                uint32_t b00 = s_B[0][row + off0];                          \
                uint32_t b01 = s_B[0][row + off4];                          \
                uint32_t b10 = s_B[1][row + off0];                          \
                uint32_t b11 = s_B[1][row + off4];                          \
                MMA_TF32(acc[0][cf], a0f, b00, b01);                        \
                MMA_TF32(acc[1][cf], a1f, b10, b11);                        \
            }                                                               \
        }

        PRELOAD(adjA, 0);
#pragma unroll
        for (int ks = 0; ks < KC / 8; ks += 2) {
            PRELOAD(adjB, ks + 1);
            COMPUTE(adjA, ks);
            if (ks + 2 < KC / 8) PRELOAD(adjA, ks + 2);
            COMPUTE(adjB, ks + 1);
        }
#undef PRELOAD
#undef COMPUTE
    }

#pragma unroll
    for (int bi = 0; bi < 2; bi++) {
        float* dst = g_part[z] + (((size_t)(2 * bp + bi) * C_) << 12);
#pragma unroll
        for (int cf = 0; cf < 4; cf++) {
            int c0 = cf * 8 + 2 * r;
            int m0 = mb + q;
            dst[((size_t)c0 << 12) + m0] = acc[bi][cf][0];
            dst[((size_t)(c0 + 1) << 12) + m0] = acc[bi][cf][1];
            dst[((size_t)c0 << 12) + m0 + 8] = acc[bi][cf][2];
            dst[((size_t)(c0 + 1) << 12) + m0 + 8] = acc[bi][cf][3];
        }
    }
}

__global__ void combine_kernel(const float* __restrict__ para,
                               float* __restrict__ out) {
    int idx = blockIdx.x * blockDim.x + threadIdx.x;
    const float4* pp = reinterpret_cast<const float4*>(para);
    float4 s = reinterpret_cast<const float4*>(g_part[0])[idx];
#pragma unroll
    for (int z = 1; z < SPLIT; z++) {
        float4 v = reinterpret_cast<const float4*>(g_part[z])[idx];
        s.x += v.x; s.y += v.y; s.z += v.z; s.w += v.w;
    }
    float4 pv = pp[idx & (C_ * N_ / 4 - 1)];
    float4 o;
    o.x = fmaxf(2.0f * s.x * pv.x, 0.f);
    o.y = fmaxf(2.0f * s.y * pv.y, 0.f);
    o.z = fmaxf(2.0f * s.z * pv.z, 0.f);
    o.w = fmaxf(2.0f * s.w * pv.w, 0.f);
    reinterpret_cast<float4*>(out)[idx] = o;
}

extern "C" void kernel_launch(void* const* d_in, const int* in_sizes, int n_in,
                              void* d_out, int out_size) {
    const float* x    = (const float*)d_in[0];  // [8,32,64,64]
    const float* para = (const float*)d_in[1];  // [1,32,64,64]
    const float* adj  = (const float*)d_in[2];  // [4096,4096]
    float* out = (float*)d_out;

    mean_exp_kernel<<<(B_ * N_ + 255) / 256, 256>>>(x);

    dim3 grid(N_ / 128, B_ / 2, SPLIT);
    gcn_mma_kernel<<<grid, 256>>>(x, adj);

    combine_kernel<<<(B_ * C_ * N_ / 4) / 256, 256>>>(para, out);
}

// round 9
// speedup vs baseline: 1.3926x; 1.3926x over previous
#include <cuda_runtime.h>
#include <cstdint>

#define B_ 8
#define C_ 32
#define N_ 4096
#define KC 64
#define SPLIT 4

__device__ float g_e[B_ * N_];
__device__ float g_part[SPLIT][B_ * C_ * N_];

__global__ void mean_exp_kernel(const float* __restrict__ x) {
    int idx = blockIdx.x * blockDim.x + threadIdx.x;
    if (idx >= B_ * N_) return;
    int b = idx >> 12, n = idx & (N_ - 1);
    const float* p = x + ((size_t)b * C_) * N_ + n;
    float s = 0.f;
#pragma unroll
    for (int c = 0; c < C_; c++) s += p[(size_t)c * N_];
    g_e[idx] = __expf(s * (1.0f / C_));
}

__device__ __forceinline__ uint32_t pack_f16(float hi, float lo) {
    uint32_t d;
    asm("cvt.rn.f16x2.f32 %0, %1, %2;" : "=r"(d) : "f"(hi), "f"(lo));
    return d;
}

#define MMA_F16(acc, a, b0v, b1v)                                           \
    asm volatile(                                                           \
        "mma.sync.aligned.m16n8k16.row.col.f32.f16.f16.f32 "                \
        "{%0,%1,%2,%3}, {%4,%5,%6,%7}, {%8,%9}, {%0,%1,%2,%3};"             \
        : "+f"((acc)[0]), "+f"((acc)[1]), "+f"((acc)[2]), "+f"((acc)[3])    \
        : "r"((a)[0]), "r"((a)[1]), "r"((a)[2]), "r"((a)[3]),               \
          "r"(b0v), "r"(b1v))

// W[m,n] = min(e_n,e_m)/(e_n+e_m) * adj[n,m]; out^T = 2*para*(W @ fea^T)
__global__ __launch_bounds__(256, 2)
void gcn_mma_kernel(const float* __restrict__ x,
                    const float* __restrict__ adj) {
    __shared__ uint32_t s_B[2][32 * 32];   // [batch][c*32 + swz(npair)], fp16x2
    __shared__ float s_e[2][KC];

    const int tid = threadIdx.x;
    const int warp = tid >> 5;
    const int lane = tid & 31;
    const int q = lane >> 2;
    const int r = lane & 3;
    const int mb = blockIdx.x * 128 + warp * 16;
    const int bp = blockIdx.y;
    const int b0 = 2 * bp, b1 = 2 * bp + 1;
    const int z = blockIdx.z;
    const int nbeg = z * (N_ / SPLIT);
    const int nend = nbeg + (N_ / SPLIT);

    const float em0a = g_e[b0 * N_ + mb + q];
    const float em0b = g_e[b0 * N_ + mb + q + 8];
    const float em1a = g_e[b1 * N_ + mb + q];
    const float em1b = g_e[b1 * N_ + mb + q + 8];

    float acc[2][4][4];
#pragma unroll
    for (int bi = 0; bi < 2; bi++)
#pragma unroll
        for (int cf = 0; cf < 4; cf++)
#pragma unroll
            for (int i = 0; i < 4; i++) acc[bi][cf][i] = 0.f;

    // staging: 2 batches x 32c x 64n = 4096 floats -> 2048 fp16 pairs; 16 floats/thread
    const int st_b = tid >> 7;
    const int st_c = (tid >> 2) & 31;
    const int st_p0 = (tid & 3) * 8;        // first of 8 pair-words
    const float* st_x = x + (((size_t)(2 * bp + st_b) * C_ + st_c) << 12);
    const int st_sw = 4 * (st_c & 7);

    for (int n0 = nbeg; n0 < nend; n0 += KC) {
        __syncthreads();
        {
            uint32_t pr[8];
#pragma unroll
            for (int j = 0; j < 4; j++) {
                float4 u = *reinterpret_cast<const float4*>(
                    st_x + n0 + st_p0 * 2 + 4 * j);
                pr[2 * j]     = pack_f16(u.y, u.x);
                pr[2 * j + 1] = pack_f16(u.w, u.z);
            }
            uint32_t* dst = &s_B[st_b][st_c * 32];
            *reinterpret_cast<uint4*>(&dst[(st_p0 + st_sw) & 31]) =
                make_uint4(pr[0], pr[1], pr[2], pr[3]);
            *reinterpret_cast<uint4*>(&dst[(st_p0 + 4 + st_sw) & 31]) =
                make_uint4(pr[4], pr[5], pr[6], pr[7]);
            if (tid < 128)
                s_e[tid >> 6][tid & 63] =
                    g_e[(2 * bp + (tid >> 6)) * N_ + n0 + (tid & 63)];
        }
        __syncthreads();

        const float* ap = adj + (size_t)(n0 + 2 * r) * N_ + mb + q;

#pragma unroll
        for (int ks = 0; ks < KC / 16; ks++) {
            const int k0 = ks * 16;
            const float* ab = ap + (size_t)k0 * N_;
            // adj for kk slots {2r, 2r+1, 2r+8, 2r+9} x m rows {q, q+8}
            float g[4][2];
            g[0][0] = __ldg(ab);
            g[0][1] = __ldg(ab + 8);
            g[1][0] = __ldg(ab + (size_t)N_);
            g[1][1] = __ldg(ab + (size_t)N_ + 8);
            g[2][0] = __ldg(ab + (size_t)8 * N_);
            g[2][1] = __ldg(ab + (size_t)8 * N_ + 8);
            g[3][0] = __ldg(ab + (size_t)9 * N_);
            g[3][1] = __ldg(ab + (size_t)9 * N_ + 8);

            float en0[4], en1[4];
            en0[0] = s_e[0][k0 + 2 * r];     en1[0] = s_e[1][k0 + 2 * r];
            en0[1] = s_e[0][k0 + 2 * r + 1]; en1[1] = s_e[1][k0 + 2 * r + 1];
            en0[2] = s_e[0][k0 + 2 * r + 8]; en1[2] = s_e[1][k0 + 2 * r + 8];
            en0[3] = s_e[0][k0 + 2 * r + 9]; en1[3] = s_e[1][k0 + 2 * r + 9];

            float w0[4][2], w1[4][2];
#pragma unroll
            for (int kk = 0; kk < 4; kk++) {
#pragma unroll
                for (int mm = 0; mm < 2; mm++) {
                    const float e0 = mm ? em0b : em0a;
                    const float e1 = mm ? em1b : em1a;
                    float d0 = en0[kk] + e0, d1 = en1[kk] + e1;
                    float rr;
                    asm("rcp.approx.f32 %0, %1;" : "=f"(rr) : "f"(d0 * d1));
                    float ra = g[kk][mm] * rr;
                    w0[kk][mm] = fminf(en0[kk], e0) * d1 * ra;
                    w1[kk][mm] = fminf(en1[kk], e1) * d0 * ra;
                }
            }
            // A regs: {row q k-lo, row q+8 k-lo, row q k-hi, row q+8 k-hi}
            uint32_t a0[4], a1[4];
            a0[0] = pack_f16(w0[1][0], w0[0][0]);
            a0[1] = pack_f16(w0[1][1], w0[0][1]);
            a0[2] = pack_f16(w0[3][0], w0[2][0]);
            a0[3] = pack_f16(w0[3][1], w0[2][1]);
            a1[0] = pack_f16(w1[1][0], w1[0][0]);
            a1[1] = pack_f16(w1[1][1], w1[0][1]);
            a1[2] = pack_f16(w1[3][0], w1[2][0]);
            a1[3] = pack_f16(w1[3][1], w1[2][1]);

            const int kp0 = ks * 8;
            const int off0 = (kp0 + r + 4 * q) & 31;
            const int off4 = (kp0 + r + 4 + 4 * q) & 31;
#pragma unroll
            for (int cf = 0; cf < 4; cf++) {
                const int row = (cf * 8 + q) * 32;
                uint32_t b00 = s_B[0][row + off0];
                uint32_t b01 = s_B[0][row + off4];
                uint32_t b10 = s_B[1][row + off0];
                uint32_t b11 = s_B[1][row + off4];
                MMA_F16(acc[0][cf], a0, b00, b01);
                MMA_F16(acc[1][cf], a1, b10, b11);
            }
        }
    }

#pragma unroll
    for (int bi = 0; bi < 2; bi++) {
        float* dst = g_part[z] + (((size_t)(2 * bp + bi) * C_) << 12);
#pragma unroll
        for (int cf = 0; cf < 4; cf++) {
            int c0 = cf * 8 + 2 * r;
            int m0 = mb + q;
            dst[((size_t)c0 << 12) + m0] = acc[bi][cf][0];
            dst[((size_t)(c0 + 1) << 12) + m0] = acc[bi][cf][1];
            dst[((size_t)c0 << 12) + m0 + 8] = acc[bi][cf][2];
            dst[((size_t)(c0 + 1) << 12) + m0 + 8] = acc[bi][cf][3];
        }
    }
}

__global__ void combine_kernel(const float* __restrict__ para,
                               float* __restrict__ out) {
    int idx = blockIdx.x * blockDim.x + threadIdx.x;
    const float4* pp = reinterpret_cast<const float4*>(para);
    float4 s = reinterpret_cast<const float4*>(g_part[0])[idx];
#pragma unroll
    for (int z = 1; z < SPLIT; z++) {
        float4 v = reinterpret_cast<const float4*>(g_part[z])[idx];
        s.x += v.x; s.y += v.y; s.z += v.z; s.w += v.w;
    }
    float4 pv = pp[idx & (C_ * N_ / 4 - 1)];
    float4 o;
    o.x = fmaxf(2.0f * s.x * pv.x, 0.f);
    o.y = fmaxf(2.0f * s.y * pv.y, 0.f);
    o.z = fmaxf(2.0f * s.z * pv.z, 0.f);
    o.w = fmaxf(2.0f * s.w * pv.w, 0.f);
    reinterpret_cast<float4*>(out)[idx] = o;
}

extern "C" void kernel_launch(void* const* d_in, const int* in_sizes, int n_in,
                              void* d_out, int out_size) {
    const float* x    = (const float*)d_in[0];  // [8,32,64,64]
    const float* para = (const float*)d_in[1];  // [1,32,64,64]
    const float* adj  = (const float*)d_in[2];  // [4096,4096]
    float* out = (float*)d_out;

    mean_exp_kernel<<<(B_ * N_ + 255) / 256, 256>>>(x);

    dim3 grid(N_ / 128, B_ / 2, SPLIT);
    gcn_mma_kernel<<<grid, 256>>>(x, adj);

    combine_kernel<<<(B_ * C_ * N_ / 4) / 256, 256>>>(para, out);
}

// round 10
// speedup vs baseline: 1.4444x; 1.0372x over previous
#include <cuda_runtime.h>
#include <cstdint>

#define B_ 8
#define C_ 32
#define N_ 4096
#define KC 64
#define SPLIT 4

__device__ float g_e[B_ * N_];
__device__ float g_part[SPLIT][B_ * C_ * N_];

__global__ void mean_exp_kernel(const float* __restrict__ x) {
    int idx = blockIdx.x * blockDim.x + threadIdx.x;
    if (idx >= B_ * N_) return;
    int b = idx >> 12, n = idx & (N_ - 1);
    const float* p = x + ((size_t)b * C_) * N_ + n;
    float s = 0.f;
#pragma unroll
    for (int c = 0; c < C_; c++) s += p[(size_t)c * N_];
    g_e[idx] = __expf(s * (1.0f / C_));
}

__device__ __forceinline__ uint32_t pack_f16(float hi, float lo) {
    uint32_t d;
    asm("cvt.rn.f16x2.f32 %0, %1, %2;" : "=r"(d) : "f"(hi), "f"(lo));
    return d;
}

#define MMA_F16(acc, a, b0v, b1v)                                           \
    asm volatile(                                                           \
        "mma.sync.aligned.m16n8k16.row.col.f32.f16.f16.f32 "                \
        "{%0,%1,%2,%3}, {%4,%5,%6,%7}, {%8,%9}, {%0,%1,%2,%3};"             \
        : "+f"((acc)[0]), "+f"((acc)[1]), "+f"((acc)[2]), "+f"((acc)[3])    \
        : "r"((a)[0]), "r"((a)[1]), "r"((a)[2]), "r"((a)[3]),               \
          "r"(b0v), "r"(b1v))

__global__ __launch_bounds__(256, 2)
void gcn_mma_kernel(const float* __restrict__ x,
                    const float* __restrict__ adj) {
    __shared__ uint32_t s_B[2][2][32 * 32];  // [buf][batch][c*32 + swz(npair)]
    __shared__ float s_e[2][2][KC];

    const int tid = threadIdx.x;
    const int warp = tid >> 5;
    const int lane = tid & 31;
    const int q = lane >> 2;
    const int r = lane & 3;
    const int mb = blockIdx.x * 128 + warp * 16;
    const int bp = blockIdx.y;
    const int b0 = 2 * bp, b1 = 2 * bp + 1;
    const int z = blockIdx.z;
    const int nbeg = z * (N_ / SPLIT);
    const int nend = nbeg + (N_ / SPLIT);

    const float em0a = g_e[b0 * N_ + mb + q];
    const float em0b = g_e[b0 * N_ + mb + q + 8];
    const float em1a = g_e[b1 * N_ + mb + q];
    const float em1b = g_e[b1 * N_ + mb + q + 8];

    float acc[2][4][4];
#pragma unroll
    for (int bi = 0; bi < 2; bi++)
#pragma unroll
        for (int cf = 0; cf < 4; cf++)
#pragma unroll
            for (int i = 0; i < 4; i++) acc[bi][cf][i] = 0.f;

    const int st_b = tid >> 7;
    const int st_c = (tid >> 2) & 31;
    const int st_p0 = (tid & 3) * 8;
    const float* st_x = x + (((size_t)(2 * bp + st_b) * C_ + st_c) << 12);
    const int st_sw = 4 * (st_c & 7);

#define STAGE_STORE(BUF, U, EV)                                             \
    {                                                                       \
        uint32_t* dst = &s_B[BUF][st_b][st_c * 32];                         \
        uint32_t pr[8];                                                     \
        _Pragma("unroll")                                                   \
        for (int j = 0; j < 4; j++) {                                       \
            pr[2 * j]     = pack_f16(U[j].y, U[j].x);                       \
            pr[2 * j + 1] = pack_f16(U[j].w, U[j].z);                       \
        }                                                                   \
        *reinterpret_cast<uint4*>(&dst[(st_p0 + st_sw) & 31]) =             \
            make_uint4(pr[0], pr[1], pr[2], pr[3]);                         \
        *reinterpret_cast<uint4*>(&dst[(st_p0 + 4 + st_sw) & 31]) =         \
            make_uint4(pr[4], pr[5], pr[6], pr[7]);                         \
        if (tid < 128) s_e[BUF][tid >> 6][tid & 63] = EV;                   \
    }

#define STAGE_LOAD(U, EV, NBASE)                                            \
    {                                                                       \
        _Pragma("unroll")                                                   \
        for (int j = 0; j < 4; j++)                                         \
            U[j] = *reinterpret_cast<const float4*>(                        \
                st_x + (NBASE) + st_p0 * 2 + 4 * j);                        \
        if (tid < 128)                                                      \
            EV = g_e[(2 * bp + (tid >> 6)) * N_ + (NBASE) + (tid & 63)];    \
    }

#define PRELOAD_ADJ(G, AP, KS)                                              \
    {                                                                       \
        const float* ab = (AP) + (size_t)((KS) * 16) * N_;                  \
        G[0][0] = __ldg(ab);                                                \
        G[0][1] = __ldg(ab + 8);                                            \
        G[1][0] = __ldg(ab + (size_t)N_);                                   \
        G[1][1] = __ldg(ab + (size_t)N_ + 8);                               \
        G[2][0] = __ldg(ab + (size_t)8 * N_);                               \
        G[2][1] = __ldg(ab + (size_t)8 * N_ + 8);                           \
        G[3][0] = __ldg(ab + (size_t)9 * N_);                               \
        G[3][1] = __ldg(ab + (size_t)9 * N_ + 8);                           \
    }

#define COMPUTE_KS(G, BUF, KS)                                              \
    {                                                                       \
        const int k0 = (KS) * 16;                                           \
        float en0[4], en1[4];                                               \
        en0[0] = s_e[BUF][0][k0 + 2 * r];                                   \
        en1[0] = s_e[BUF][1][k0 + 2 * r];                                   \
        en0[1] = s_e[BUF][0][k0 + 2 * r + 1];                               \
        en1[1] = s_e[BUF][1][k0 + 2 * r + 1];                               \
        en0[2] = s_e[BUF][0][k0 + 2 * r + 8];                               \
        en1[2] = s_e[BUF][1][k0 + 2 * r + 8];                               \
        en0[3] = s_e[BUF][0][k0 + 2 * r + 9];                               \
        en1[3] = s_e[BUF][1][k0 + 2 * r + 9];                               \
        float w0[4][2], w1[4][2];                                           \
        _Pragma("unroll")                                                   \
        for (int kk = 0; kk < 4; kk++) {                                    \
            _Pragma("unroll")                                               \
            for (int mm = 0; mm < 2; mm++) {                                \
                const float e0 = mm ? em0b : em0a;                          \
                const float e1 = mm ? em1b : em1a;                          \
                float d0 = en0[kk] + e0, d1 = en1[kk] + e1;                 \
                float rr;                                                   \
                asm("rcp.approx.f32 %0, %1;" : "=f"(rr) : "f"(d0 * d1));    \
                float ra = G[kk][mm] * rr;                                  \
                w0[kk][mm] = fminf(en0[kk], e0) * d1 * ra;                  \
                w1[kk][mm] = fminf(en1[kk], e1) * d0 * ra;                  \
            }                                                               \
        }                                                                   \
        uint32_t a0[4], a1[4];                                              \
        a0[0] = pack_f16(w0[1][0], w0[0][0]);                               \
        a0[1] = pack_f16(w0[1][1], w0[0][1]);                               \
        a0[2] = pack_f16(w0[3][0], w0[2][0]);                               \
        a0[3] = pack_f16(w0[3][1], w0[2][1]);                               \
        a1[0] = pack_f16(w1[1][0], w1[0][0]);                               \
        a1[1] = pack_f16(w1[1][1], w1[0][1]);                               \
        a1[2] = pack_f16(w1[3][0], w1[2][0]);                               \
        a1[3] = pack_f16(w1[3][1], w1[2][1]);                               \
        const int kp0 = (KS) * 8;                                           \
        const int off0 = (kp0 + r + 4 * q) & 31;                            \
        const int off4 = (kp0 + r + 4 + 4 * q) & 31;                        \
        _Pragma("unroll")                                                   \
        for (int cf = 0; cf < 4; cf++) {                                    \
            const int row = (cf * 8 + q) * 32;                              \
            uint32_t b00 = s_B[BUF][0][row + off0];                         \
            uint32_t b01 = s_B[BUF][0][row + off4];                         \
            uint32_t b10 = s_B[BUF][1][row + off0];                         \
            uint32_t b11 = s_B[BUF][1][row + off4];                         \
            MMA_F16(acc[0][cf], a0, b00, b01);                              \
            MMA_F16(acc[1][cf], a1, b10, b11);                              \
        }                                                                   \
    }

    // prologue: stage first chunk
    {
        float4 u[4];
        float ev = 0.f;
        STAGE_LOAD(u, ev, nbeg);
        STAGE_STORE(0, u, ev);
    }
    __syncthreads();

    int cur = 0;
    for (int n0 = nbeg; n0 < nend; n0 += KC) {
        const int n1 = n0 + KC;
        const bool has_next = (n1 < nend);

        float4 u[4];
        float ev = 0.f;
        if (has_next) STAGE_LOAD(u, ev, n1);   // LDGs issued early, hidden by compute

        const float* ap = adj + (size_t)(n0 + 2 * r) * N_ + mb + q;
        float gA[4][2], gB[4][2];
        PRELOAD_ADJ(gA, ap, 0);
        PRELOAD_ADJ(gB, ap, 1);
        COMPUTE_KS(gA, cur, 0);
        PRELOAD_ADJ(gA, ap, 2);
        COMPUTE_KS(gB, cur, 1);
        PRELOAD_ADJ(gB, ap, 3);
        COMPUTE_KS(gA, cur, 2);
        COMPUTE_KS(gB, cur, 3);

        if (has_next) STAGE_STORE(cur ^ 1, u, ev);
        __syncthreads();
        cur ^= 1;
    }

#pragma unroll
    for (int bi = 0; bi < 2; bi++) {
        float* dst = g_part[z] + (((size_t)(2 * bp + bi) * C_) << 12);
#pragma unroll
        for (int cf = 0; cf < 4; cf++) {
            int c0 = cf * 8 + 2 * r;
            int m0 = mb + q;
            dst[((size_t)c0 << 12) + m0] = acc[bi][cf][0];
            dst[((size_t)(c0 + 1) << 12) + m0] = acc[bi][cf][1];
            dst[((size_t)c0 << 12) + m0 + 8] = acc[bi][cf][2];
            dst[((size_t)(c0 + 1) << 12) + m0 + 8] = acc[bi][cf][3];
        }
    }
}

__global__ void combine_kernel(const float* __restrict__ para,
                               float* __restrict__ out) {
    int idx = blockIdx.x * blockDim.x + threadIdx.x;
    const float4* pp = reinterpret_cast<const float4*>(para);
    float4 s = reinterpret_cast<const float4*>(g_part[0])[idx];
#pragma unroll
    for (int z = 1; z < SPLIT; z++) {
        float4 v = reinterpret_cast<const float4*>(g_part[z])[idx];
        s.x += v.x; s.y += v.y; s.z += v.z; s.w += v.w;
    }
    float4 pv = pp[idx & (C_ * N_ / 4 - 1)];
    float4 o;
    o.x = fmaxf(2.0f * s.x * pv.x, 0.f);
    o.y = fmaxf(2.0f * s.y * pv.y, 0.f);
    o.z = fmaxf(2.0f * s.z * pv.z, 0.f);
    o.w = fmaxf(2.0f * s.w * pv.w, 0.f);
    reinterpret_cast<float4*>(out)[idx] = o;
}

extern "C" void kernel_launch(void* const* d_in, const int* in_sizes, int n_in,
                              void* d_out, int out_size) {
    const float* x    = (const float*)d_in[0];  // [8,32,64,64]
    const float* para = (const float*)d_in[1];  // [1,32,64,64]
    const float* adj  = (const float*)d_in[2];  // [4096,4096]
    float* out = (float*)d_out;

    mean_exp_kernel<<<(B_ * N_ + 255) / 256, 256>>>(x);

    dim3 grid(N_ / 128, B_ / 2, SPLIT);
    gcn_mma_kernel<<<grid, 256>>>(x, adj);

    combine_kernel<<<(B_ * C_ * N_ / 4) / 256, 256>>>(para, out);
}